// round 1
// baseline (speedup 1.0000x reference)
#include <cuda_runtime.h>

// Constants from reference
#define BOHR        0.52917721067f
#define A_MUTUAL    0.39f

// inputs (metadata order):
// 0: species        int32  [N]
// 1: edge_src       int32  [E]
// 2: edge_dst       int32  [E]
// 3: distances      f32    [E]
// 4: vec            f32    [E,3]
// 5: polarisability f32    [N]
// 6: mu             f32    [N,3]
// out: f32 [N,3]

__global__ void init_out_kernel(const float* __restrict__ pol,
                                const float* __restrict__ mu,
                                float* __restrict__ out,
                                int n_nodes)
{
    int i = blockIdx.x * blockDim.x + threadIdx.x;
    if (i >= n_nodes) return;
    // pol_bohr = pol / BOHR^3  =>  mu / pol_bohr = mu * BOHR^3 / pol
    const float bohr3 = BOHR * BOHR * BOHR;
    float inv_pol = bohr3 / pol[i];
    out[3 * i + 0] = mu[3 * i + 0] * inv_pol;
    out[3 * i + 1] = mu[3 * i + 1] * inv_pol;
    out[3 * i + 2] = mu[3 * i + 2] * inv_pol;
}

__global__ void edge_kernel(const int*   __restrict__ edge_src,
                            const int*   __restrict__ edge_dst,
                            const float* __restrict__ distances,
                            const float* __restrict__ vec,
                            const float* __restrict__ pol,
                            const float* __restrict__ mu,
                            float* __restrict__ out,
                            int n_edges)
{
    const float inv_bohr  = 1.0f / BOHR;
    const float inv_bohr3 = inv_bohr * inv_bohr * inv_bohr;

    int e = blockIdx.x * blockDim.x + threadIdx.x;
    if (e >= n_edges) return;

    int src = edge_src[e];
    int dst = edge_dst[e];

    float rij = distances[e] * inv_bohr;

    // vec in bohr
    float vx = vec[3 * e + 0] * inv_bohr;
    float vy = vec[3 * e + 1] * inv_bohr;
    float vz = vec[3 * e + 2] * inv_bohr;

    // pol in bohr^3 (gathered, L2-resident)
    float pol_s = pol[src] * inv_bohr3;
    float pol_d = pol[dst] * inv_bohr3;

    // alpha_ij^(1/2); au3 = A * rij^3 / sqrt(alpha_ij)
    float inv_sqrt_alpha = rsqrtf(pol_s * pol_d);
    float rij2 = rij * rij;
    float rij3 = rij2 * rij;
    float au3  = A_MUTUAL * rij3 * inv_sqrt_alpha;

    float eexp = expf(-au3);
    float lam3 = 1.0f - eexp;
    float lam5 = 1.0f - (1.0f + au3) * eexp;

    float inv_r3 = 1.0f / rij3;
    float inv_r5 = inv_r3 / rij2;

    // mu[dst] gather (L2-resident)
    float mx = mu[3 * dst + 0];
    float my = mu[3 * dst + 1];
    float mz = mu[3 * dst + 2];

    float dot = vx * mx + vy * my + vz * mz;

    float c3 = lam3 * inv_r3;
    float c5 = 3.0f * lam5 * inv_r5 * dot;

    float cx = c3 * mx - c5 * vx;
    float cy = c3 * my - c5 * vy;
    float cz = c3 * mz - c5 * vz;

    atomicAdd(&out[3 * src + 0], cx);
    atomicAdd(&out[3 * src + 1], cy);
    atomicAdd(&out[3 * src + 2], cz);
}

extern "C" void kernel_launch(void* const* d_in, const int* in_sizes, int n_in,
                              void* d_out, int out_size)
{
    const int*   edge_src = (const int*)  d_in[1];
    const int*   edge_dst = (const int*)  d_in[2];
    const float* dists    = (const float*)d_in[3];
    const float* vec      = (const float*)d_in[4];
    const float* pol      = (const float*)d_in[5];
    const float* mu       = (const float*)d_in[6];
    float*       out      = (float*)d_out;

    int n_edges = in_sizes[3];
    int n_nodes = in_sizes[5];

    int tb = 256;
    init_out_kernel<<<(n_nodes + tb - 1) / tb, tb>>>(pol, mu, out, n_nodes);
    edge_kernel<<<(n_edges + tb - 1) / tb, tb>>>(edge_src, edge_dst, dists, vec,
                                                 pol, mu, out, n_edges);
}

// round 2
// speedup vs baseline: 1.8547x; 1.8547x over previous
#include <cuda_runtime.h>

#define BOHR        0.52917721067f
#define A_MUTUAL    0.39f
#define MAX_NODES   262144

// Scratch: packed per-node data and vector accumulator (no allocations allowed).
__device__ float4 g_pack[MAX_NODES];  // {mu.x, mu.y, mu.z, rsqrt(pol_bohr)}
__device__ float4 g_acc[MAX_NODES];   // field accumulator (w unused)

__global__ void pack_kernel(const float* __restrict__ pol,
                            const float* __restrict__ mu,
                            int n_nodes)
{
    int i = blockIdx.x * blockDim.x + threadIdx.x;
    if (i >= n_nodes) return;
    const float inv_bohr3 = 1.0f / (BOHR * BOHR * BOHR);
    float pb = pol[i] * inv_bohr3;                 // pol in bohr^3
    float4 p;
    p.x = mu[3 * i + 0];
    p.y = mu[3 * i + 1];
    p.z = mu[3 * i + 2];
    p.w = rsqrtf(pb);                              // pol_bohr^{-1/2}
    g_pack[i] = p;
    g_acc[i]  = make_float4(0.f, 0.f, 0.f, 0.f);
}

__global__ void edge_kernel(const int*   __restrict__ edge_src,
                            const int*   __restrict__ edge_dst,
                            const float* __restrict__ distances,
                            const float* __restrict__ vec,
                            int n_edges)
{
    const float inv_bohr = 1.0f / BOHR;

    int e = blockIdx.x * blockDim.x + threadIdx.x;
    if (e >= n_edges) return;

    int src = edge_src[e];
    int dst = edge_dst[e];

    float rij = distances[e] * inv_bohr;

    float vx = vec[3 * e + 0] * inv_bohr;
    float vy = vec[3 * e + 1] * inv_bohr;
    float vz = vec[3 * e + 2] * inv_bohr;

    // One 16B gather for dst (mu + q), one 4B gather for src (q only).
    float4 pd = __ldg(&g_pack[dst]);
    float  qs = __ldg(&g_pack[src].w);

    float inv_sqrt_alpha = qs * pd.w;              // (pol_s*pol_d)^{-1/2}
    float rij2 = rij * rij;
    float rij3 = rij2 * rij;
    float au3  = A_MUTUAL * rij3 * inv_sqrt_alpha;

    float eexp = __expf(-au3);
    float lam3 = 1.0f - eexp;
    float lam5 = 1.0f - (1.0f + au3) * eexp;

    float inv_r3 = 1.0f / rij3;
    float inv_r5 = inv_r3 / rij2;

    float dot = vx * pd.x + vy * pd.y + vz * pd.z;

    float c3 = lam3 * inv_r3;
    float c5 = 3.0f * lam5 * inv_r5 * dot;

    float cx = c3 * pd.x - c5 * vx;
    float cy = c3 * pd.y - c5 * vy;
    float cz = c3 * pd.z - c5 * vz;

    // Single vector reduction op (sm_90+): 1 LTS op instead of 3.
    float4* dstp = &g_acc[src];
    asm volatile("red.global.add.v4.f32 [%0], {%1, %2, %3, %4};"
                 :: "l"(dstp), "f"(cx), "f"(cy), "f"(cz), "f"(0.0f)
                 : "memory");
}

__global__ void final_kernel(const float* __restrict__ pol,
                             const float* __restrict__ mu,
                             float* __restrict__ out,
                             int n_nodes)
{
    int i = blockIdx.x * blockDim.x + threadIdx.x;
    if (i >= n_nodes) return;
    const float bohr3 = BOHR * BOHR * BOHR;
    float inv_pol = bohr3 / pol[i];                // = 1/pol_bohr
    float4 a = g_acc[i];
    out[3 * i + 0] = mu[3 * i + 0] * inv_pol + a.x;
    out[3 * i + 1] = mu[3 * i + 1] * inv_pol + a.y;
    out[3 * i + 2] = mu[3 * i + 2] * inv_pol + a.z;
}

extern "C" void kernel_launch(void* const* d_in, const int* in_sizes, int n_in,
                              void* d_out, int out_size)
{
    const int*   edge_src = (const int*)  d_in[1];
    const int*   edge_dst = (const int*)  d_in[2];
    const float* dists    = (const float*)d_in[3];
    const float* vec      = (const float*)d_in[4];
    const float* pol      = (const float*)d_in[5];
    const float* mu       = (const float*)d_in[6];
    float*       out      = (float*)d_out;

    int n_edges = in_sizes[3];
    int n_nodes = in_sizes[5];

    int tb = 256;
    pack_kernel<<<(n_nodes + tb - 1) / tb, tb>>>(pol, mu, n_nodes);
    edge_kernel<<<(n_edges + tb - 1) / tb, tb>>>(edge_src, edge_dst, dists, vec, n_edges);
    final_kernel<<<(n_nodes + tb - 1) / tb, tb>>>(pol, mu, out, n_nodes);
}